// round 13
// baseline (speedup 1.0000x reference)
#include <cuda_runtime.h>
#include <cuda_fp16.h>
#include <cstdint>

#define ROWS_TOT 40000
#define ROWS_SF  20000
#define ROWS_PAD 40064        // 626 * 64

// ---------------- scratch (static device globals; no runtime allocation) ----------------
__device__ float g_psum_p[160 * 1024];     // per-(batch,chunk) partial sums, no zeroing needed
__device__ float g_cnt_p[160];
__device__ float g_pvec[8 * 1024];
__device__ float g_a[ROWS_PAD];
__device__ __align__(16) __half g_fh[(size_t)ROWS_PAD * 1024];   // pre-converted features
__device__ __align__(16) __half g_wd[16 * 64 * 64];   // [chunk][n][k] fp16
__device__ __align__(16) __half g_wu[1024 * 64];      // [n][k] fp16 (chunk = n/64)

// ---------------- helpers ----------------
__device__ __forceinline__ void mma_f16(float* d, uint32_t a0, uint32_t a1, uint32_t a2,
                                        uint32_t a3, uint32_t b0, uint32_t b1) {
    asm volatile(
        "mma.sync.aligned.m16n8k16.row.col.f32.f16.f16.f32 "
        "{%0,%1,%2,%3}, {%4,%5,%6,%7}, {%8,%9}, {%0,%1,%2,%3};"
        : "+f"(d[0]), "+f"(d[1]), "+f"(d[2]), "+f"(d[3])
        : "r"(a0), "r"(a1), "r"(a2), "r"(a3), "r"(b0), "r"(b1));
}
__device__ __forceinline__ void ldsm_x4(uint32_t addr, uint32_t* r) {
    asm volatile("ldmatrix.sync.aligned.m8n8.x4.shared.b16 {%0,%1,%2,%3}, [%4];"
                 : "=r"(r[0]), "=r"(r[1]), "=r"(r[2]), "=r"(r[3]) : "r"(addr));
}
__device__ __forceinline__ uint32_t smem_u32(const void* p) {
    uint32_t a;
    asm("{ .reg .u64 t; cvta.to.shared.u64 t, %1; cvt.u32.u64 %0, t; }" : "=r"(a) : "l"(p));
    return a;
}
__device__ __forceinline__ uint32_t pkh2(float x, float y) {
    __half2 h = __float22half2_rn(make_float2(x, y));
    return *reinterpret_cast<uint32_t*>(&h);
}
__device__ __forceinline__ void cpasync16(uint32_t saddr, const void* gaddr) {
    asm volatile("cp.async.cg.shared.global [%0], [%1], 16;" :: "r"(saddr), "l"(gaddr));
}
__device__ __forceinline__ void cp_commit() {
    asm volatile("cp.async.commit_group;");
}
__device__ __forceinline__ void cp_wait0() {
    asm volatile("cp.async.wait_group 0;");
}

// ---------------- K1: weight prep + masked proto partial sums (fused, no zeroing) ---------
__global__ void prep_all_k(const float* __restrict__ Wd, const float* __restrict__ Wu,
                           const float* __restrict__ s_f, const float* __restrict__ s_y) {
    const int bid = blockIdx.x, t = threadIdx.x;
    if (bid < 512) {
        int i = bid * 256 + t;
        if (i < 65536) {                       // Wd [64][1024] -> chunked [16][64][64]
            int n = i >> 10, kk = i & 1023;
            int c = kk >> 6, k = kk & 63;
            g_wd[c * 4096 + n * 64 + k] = __float2half_rn(Wd[i]);
        } else {                               // Wu [1024][64]
            int j = i - 65536;
            g_wu[j] = __float2half_rn(Wu[j]);
        }
        return;
    }
    const int p = bid - 512;                   // 0..159
    const int b = p / 20, chunk = p % 20;
    const int n0 = chunk * 125;
    const float* sy = s_y + (size_t)b * 160000;
    float4 acc = make_float4(0.f, 0.f, 0.f, 0.f);
    int cnt = 0;
    for (int n = n0; n < n0 + 125; n++) {
        float m = sy[(n / 50) * 3200 + (n % 50) * 8];   // nearest-neighbor stride-8
        if (m == 1.0f) {
            float4 v = *(const float4*)(s_f + (size_t)(b * 2500 + n) * 1024 + t * 4);
            acc.x += v.x; acc.y += v.y; acc.z += v.z; acc.w += v.w;
            cnt++;
        }
    }
    *(float4*)(g_psum_p + (size_t)p * 1024 + t * 4) = acc;
    if (t == 0) g_cnt_p[p] = (float)cnt;
}

// ---------------- K2: prototype selection (grid 8 = one CTA per batch) ----------------
__global__ void select3_k(const float* __restrict__ P) {   // P: [1024][16]
    __shared__ float psum[1024];
    __shared__ float s_sim[16], s_n2[16];
    __shared__ float scnt;
    __shared__ int   ssel;
    __shared__ float sfac;
    const int b = blockIdx.x, t = threadIdx.x, lane = t & 31, w = t >> 5;
    #pragma unroll
    for (int i = 0; i < 4; i++) {
        int d = t + i * 256;
        float s = 0.f;
        #pragma unroll
        for (int p = 0; p < 20; p++) s += g_psum_p[(size_t)(b * 20 + p) * 1024 + d];
        psum[d] = s;
    }
    if (t == 0) {
        float c = 0.f;
        #pragma unroll
        for (int p = 0; p < 20; p++) c += g_cnt_p[b * 20 + p];
        scnt = c;
    }
    __syncthreads();
    for (int c = w; c < 16; c += 8) {
        float sd = 0.f, sn = 0.f;
        for (int d = lane; d < 1024; d += 32) {
            float pv = P[d * 16 + c];
            sd = fmaf(psum[d], pv, sd);
            sn = fmaf(pv, pv, sn);
        }
        #pragma unroll
        for (int o = 16; o; o >>= 1) {
            sd += __shfl_xor_sync(0xFFFFFFFFu, sd, o);
            sn += __shfl_xor_sync(0xFFFFFFFFu, sn, o);
        }
        if (!lane) { s_sim[c] = sd; s_n2[c] = sn; }
    }
    __syncthreads();
    if (t == 0) {
        int best = 0; float bv = -1e30f;
        #pragma unroll
        for (int c = 0; c < 16; c++) {
            float v = s_sim[c] * rsqrtf(fmaxf(s_n2[c], 1e-24f));
            if (v > bv) { bv = v; best = c; }
        }
        ssel = best;
        float sign = (scnt > 0.5f) ? 1.0f : 0.0f;
        sfac = sign * 32.0f * rsqrtf(fmaxf(s_n2[best], 1e-24f));
    }
    __syncthreads();
    const int sel = ssel; const float fac = sfac;
    #pragma unroll
    for (int i = 0; i < 4; i++) {
        int d = t + i * 256;
        g_pvec[b * 1024 + d] = P[d * 16 + sel] * fac;
    }
}

// ---------------- K3: convert features to fp16 + per-row enhance scalar ----------------
__global__ void convert_k(const float* __restrict__ x, const float* __restrict__ s_f) {
    const int r = blockIdx.x * 8 + (threadIdx.x >> 5);
    const int lane = threadIdx.x & 31;
    __half* dst = g_fh + (size_t)r * 1024;
    if (r < ROWS_TOT) {
        const float* src = (r < ROWS_SF) ? s_f + (size_t)r * 1024
                                         : x + (size_t)(r - ROWS_SF) * 1024;
        const int bb = (r < ROWS_SF) ? r / 2500 : (r - ROWS_SF) / 2500;
        const float* pv = g_pvec + bb * 1024;
        float sq = 0.f, dp = 0.f;
        #pragma unroll
        for (int i = 0; i < 8; i++) {
            int c = i * 128 + lane * 4;
            float4 f = *(const float4*)(src + c);
            float4 p = *(const float4*)(pv + c);
            sq = fmaf(f.x, f.x, fmaf(f.y, f.y, fmaf(f.z, f.z, fmaf(f.w, f.w, sq))));
            dp = fmaf(f.x, p.x, fmaf(f.y, p.y, fmaf(f.z, p.z, fmaf(f.w, p.w, dp))));
            *(uint2*)(dst + c) = make_uint2(pkh2(f.x, f.y), pkh2(f.z, f.w));
        }
        #pragma unroll
        for (int o = 16; o; o >>= 1) {
            sq += __shfl_xor_sync(0xFFFFFFFFu, sq, o);
            dp += __shfl_xor_sync(0xFFFFFFFFu, dp, o);
        }
        if (!lane) {
            float g = fminf(fmaxf(dp / fmaxf(sqrtf(sq), 1e-12f), 0.0f), 6.0f);
            g_a[r] = 1.0f + g;
        }
    } else {
        #pragma unroll
        for (int i = 0; i < 8; i++)
            *(uint2*)(dst + i * 128 + lane * 4) = make_uint2(0u, 0u);
        if (!lane) g_a[r] = 1.0f;
    }
}

// ================= K4: fused down GEMM + up GEMM, BM=64, grid 626, occ 4 =================
// 256 thr = 8 warps (4 warpM x 16 rows, 2 warpN x 32 cols).
// smem byte layout (double buffered):
//   A0[0,9216) A1[9216,18432) B0[18432,27648) B1[27648,36864) sA[36864,37120)
// Row stride 144 B => conflict-free stores and ldmatrix.
#define SM_BYTES 37120
extern __shared__ uint32_t smw[];

__global__ void __launch_bounds__(256, 4)
fused3_k(const float* __restrict__ bdn, const float* __restrict__ bup,
         float* __restrict__ out) {
    uint32_t* Aw0 = smw;
    float*    sA  = (float*)(smw + 9216);

    const uint32_t sbase = smem_u32(smw);
    const int t = threadIdx.x, wid = t >> 5, lane = t & 31;
    const int warpM = wid & 3, warpN = wid >> 2;
    const int row0 = blockIdx.x * 64;

    // ldmatrix per-lane base addresses (byte), stage 0
    const int lr16 = lane & 15, lk16 = (lane >> 4) & 1;
    const uint32_t aAddr0 = sbase + (uint32_t)((warpM * 16 + lr16) * 144 + lk16 * 16);
    const int brr = warpN * 32 + ((lane >> 4) & 1) * 8 + (lane & 7);
    const uint32_t bAddr0 = sbase + 18432 + (uint32_t)(brr * 144 + ((lane >> 3) & 1) * 16);

    // cp.async segment mapping: A 512 segs (64 rows x 8), B 512 segs (64 n x 8); 2/thread each
    const int an0 = t >> 3, aq = t & 7;
    const uint32_t adst = sbase + (uint32_t)(an0 * 144 + aq * 16);
    const uint32_t bdst = sbase + 18432 + (uint32_t)(an0 * 144 + aq * 16);
    const __half* asrc = g_fh + (size_t)(row0 + an0) * 1024 + aq * 8;

    if (t < 64) sA[t] = g_a[row0 + t];

    float acc[4][4];
    #pragma unroll
    for (int i = 0; i < 4; i++)
        #pragma unroll
        for (int j = 0; j < 4; j++) acc[i][j] = 0.f;

    // ---- prologue: chunk 0 into stage 0 ----
    #pragma unroll
    for (int j = 0; j < 2; j++) {
        cpasync16(adst + (uint32_t)(j * 32) * 144, asrc + (size_t)(j * 32) * 1024);
        cpasync16(bdst + (uint32_t)(j * 32) * 144, g_wd + (an0 + j * 32) * 64 + aq * 8);
    }
    cp_commit();
    cp_wait0();
    __syncthreads();

    // ============ down phase: 16 chunks of 64, double-buffered ============
    #pragma unroll 1
    for (int c = 0; c < 16; c++) {
        const uint32_t cur = (uint32_t)(c & 1), nxt = cur ^ 1u;
        if (c < 15) {
            const __half* as = asrc + (c + 1) * 64;
            const __half* bs = g_wd + (c + 1) * 4096 + an0 * 64 + aq * 8;
            #pragma unroll
            for (int j = 0; j < 2; j++) {
                cpasync16(adst + nxt * 9216u + (uint32_t)(j * 32) * 144, as + (size_t)(j * 32) * 1024);
                cpasync16(bdst + nxt * 9216u + (uint32_t)(j * 32) * 144, bs + j * 32 * 64);
            }
            cp_commit();
        }
        {
            const uint32_t aA = aAddr0 + cur * 9216u;
            const uint32_t bA = bAddr0 + cur * 9216u;
            #pragma unroll
            for (int ks = 0; ks < 4; ks++) {
                uint32_t af[4], bf[2][4];
                ldsm_x4(aA + ks * 32, af);
                ldsm_x4(bA + ks * 32, bf[0]);
                ldsm_x4(bA + 16 * 144 + ks * 32, bf[1]);
                #pragma unroll
                for (int nt = 0; nt < 4; nt++) {
                    const int n2 = nt >> 1, s = (nt & 1) * 2;
                    mma_f16(acc[nt], af[0], af[1], af[2], af[3], bf[n2][s], bf[n2][s + 1]);
                }
            }
        }
        cp_wait0();
        __syncthreads();
    }

    // prefetch up-phase chunk 0 B into stage 0 (B planes free)
    #pragma unroll
    for (int j = 0; j < 2; j++)
        cpasync16(bdst + (uint32_t)(j * 32) * 144, g_wu + (an0 + j * 32) * 64 + aq * 8);
    cp_commit();

    // ---- down epilogue: h = relu(a*dot + b_down) -> fp16 into A stage-0 plane ----
    #pragma unroll
    for (int nt = 0; nt < 4; nt++) {
        const int c0 = warpN * 32 + nt * 8 + (lane & 3) * 2;
        const float bd0 = __ldg(bdn + c0), bd1 = __ldg(bdn + c0 + 1);
        const float* d = acc[nt];
        const int rb = warpM * 16 + (lane >> 2);
        #pragma unroll
        for (int rr = 0; rr < 2; rr++) {
            const int rloc = rb + rr * 8;
            float av2 = sA[rloc];
            float h0 = fmaxf(fmaf(av2, d[rr * 2 + 0], bd0), 0.f);
            float h1 = fmaxf(fmaf(av2, d[rr * 2 + 1], bd1), 0.f);
            Aw0[rloc * 36 + c0 / 2] = pkh2(h0, h1);
        }
    }
    cp_wait0();
    __syncthreads();   // h visible, up-B0 loaded

    // hoist up-phase A (h) fragments: invariant across all 16 N-chunks
    uint32_t afh[4][4];
    #pragma unroll
    for (int ks = 0; ks < 4; ks++)
        ldsm_x4(aAddr0 + ks * 32, afh[ks]);

    // ============ up phase: 16 N-chunks of 64, A = h (regs), B double-buffered ============
    #pragma unroll 1
    for (int nc = 0; nc < 16; nc++) {
        const uint32_t cur = (uint32_t)(nc & 1);
        if (nc < 15) {
            const __half* bs = g_wu + (nc + 1) * 4096 + an0 * 64 + aq * 8;
            const uint32_t bo = (cur ^ 1u) * 9216u;
            #pragma unroll
            for (int j = 0; j < 2; j++)
                cpasync16(bdst + bo + (uint32_t)(j * 32) * 144, bs + j * 32 * 64);
            cp_commit();
        }
        #pragma unroll
        for (int i = 0; i < 4; i++)
            #pragma unroll
            for (int j = 0; j < 4; j++) acc[i][j] = 0.f;
        {
            const uint32_t bA = bAddr0 + cur * 9216u;
            #pragma unroll
            for (int ks = 0; ks < 4; ks++) {
                uint32_t bf[2][4];
                ldsm_x4(bA + ks * 32, bf[0]);
                ldsm_x4(bA + 16 * 144 + ks * 32, bf[1]);
                #pragma unroll
                for (int nt = 0; nt < 4; nt++) {
                    const int n2 = nt >> 1, s = (nt & 1) * 2;
                    mma_f16(acc[nt], afh[ks][0], afh[ks][1], afh[ks][2], afh[ks][3],
                            bf[n2][s], bf[n2][s + 1]);
                }
            }
        }
        // epilogue: out = acc + b_up
        const int nb64 = nc * 64;
        #pragma unroll
        for (int nt = 0; nt < 4; nt++) {
            const int c0 = warpN * 32 + nt * 8 + (lane & 3) * 2;
            const float u0 = __ldg(bup + nb64 + c0), u1 = __ldg(bup + nb64 + c0 + 1);
            const float* d = acc[nt];
            const int rb = warpM * 16 + (lane >> 2);
            #pragma unroll
            for (int rr = 0; rr < 2; rr++) {
                int row = row0 + rb + rr * 8;
                if (row < ROWS_TOT) {
                    float2 v = make_float2(d[rr * 2 + 0] + u0, d[rr * 2 + 1] + u1);
                    *(float2*)(out + (size_t)row * 1024 + nb64 + c0) = v;
                }
            }
        }
        cp_wait0();
        __syncthreads();
    }
}

// ---------------- launch ----------------
extern "C" void kernel_launch(void* const* d_in, const int* in_sizes, int n_in,
                              void* d_out, int out_size) {
    (void)in_sizes; (void)n_in; (void)out_size;
    const float* x   = (const float*)d_in[0];
    const float* s_f = (const float*)d_in[1];
    const float* s_y = (const float*)d_in[2];
    const float* P   = (const float*)d_in[3];
    const float* Wd  = (const float*)d_in[4];
    const float* bd  = (const float*)d_in[5];
    const float* Wu  = (const float*)d_in[6];
    const float* bu  = (const float*)d_in[7];
    float* out = (float*)d_out;

    static bool attr_set = false;
    if (!attr_set) {
        cudaFuncSetAttribute(fused3_k, cudaFuncAttributeMaxDynamicSharedMemorySize, SM_BYTES);
        attr_set = true;
    }

    prep_all_k<<<672, 256>>>(Wd, Wu, s_f, s_y);
    select3_k<<<8, 256>>>(P);
    convert_k<<<5008, 256>>>(x, s_f);
    fused3_k<<<626, 256, SM_BYTES>>>(bd, bu, out);
}

// round 14
// speedup vs baseline: 1.0728x; 1.0728x over previous
#include <cuda_runtime.h>
#include <cuda_fp16.h>
#include <cstdint>

#define ROWS_TOT 40000
#define ROWS_SF  20000
#define ROWS_PAD 40064        // 313 * 128

// ---------------- scratch (static device globals; no runtime allocation) ----------------
__device__ float g_psum[8 * 1024];
__device__ float g_cnt[8];
__device__ float g_pvec[8 * 1024];
__device__ float g_a[ROWS_PAD];
__device__ __align__(16) __half g_fh[(size_t)ROWS_PAD * 1024];   // pre-converted features
__device__ __align__(16) __half g_wd[16 * 64 * 64];   // [chunk][n][k] fp16
__device__ __align__(16) __half g_wu[1024 * 64];      // [n][k] fp16 (chunk = n/64)

// ---------------- helpers ----------------
__device__ __forceinline__ void mma_f16(float* d, uint32_t a0, uint32_t a1, uint32_t a2,
                                        uint32_t a3, uint32_t b0, uint32_t b1) {
    asm volatile(
        "mma.sync.aligned.m16n8k16.row.col.f32.f16.f16.f32 "
        "{%0,%1,%2,%3}, {%4,%5,%6,%7}, {%8,%9}, {%0,%1,%2,%3};"
        : "+f"(d[0]), "+f"(d[1]), "+f"(d[2]), "+f"(d[3])
        : "r"(a0), "r"(a1), "r"(a2), "r"(a3), "r"(b0), "r"(b1));
}
__device__ __forceinline__ void ldsm_x4(uint32_t addr, uint32_t* r) {
    asm volatile("ldmatrix.sync.aligned.m8n8.x4.shared.b16 {%0,%1,%2,%3}, [%4];"
                 : "=r"(r[0]), "=r"(r[1]), "=r"(r[2]), "=r"(r[3]) : "r"(addr));
}
__device__ __forceinline__ uint32_t smem_u32(const void* p) {
    uint32_t a;
    asm("{ .reg .u64 t; cvta.to.shared.u64 t, %1; cvt.u32.u64 %0, t; }" : "=r"(a) : "l"(p));
    return a;
}
__device__ __forceinline__ uint32_t pkh2(float x, float y) {
    __half2 h = __float22half2_rn(make_float2(x, y));
    return *reinterpret_cast<uint32_t*>(&h);
}
__device__ __forceinline__ void cpasync16(uint32_t saddr, const void* gaddr) {
    asm volatile("cp.async.cg.shared.global [%0], [%1], 16;" :: "r"(saddr), "l"(gaddr));
}
__device__ __forceinline__ void cp_commit() {
    asm volatile("cp.async.commit_group;");
}
__device__ __forceinline__ void cp_wait0() {
    asm volatile("cp.async.wait_group 0;");
}
__device__ __forceinline__ void cp_wait1() {
    asm volatile("cp.async.wait_group 1;");
}

// ---------------- K1: weight prep + zero accumulators ----------------
// grid 514: [0,512) weights; 512,513 zero g_psum/g_cnt.
__global__ void prep_all_k(const float* __restrict__ Wd, const float* __restrict__ Wu) {
    const int bid = blockIdx.x, t = threadIdx.x;
    if (bid < 512) {
        int i = bid * 256 + t;
        if (i < 65536) {                       // Wd [64][1024] -> chunked [16][64][64]
            int n = i >> 10, kk = i & 1023;
            int c = kk >> 6, k = kk & 63;
            g_wd[c * 4096 + n * 64 + k] = __float2half_rn(Wd[i]);
        } else {                               // Wu [1024][64]
            int j = i - 65536;
            g_wu[j] = __float2half_rn(Wu[j]);
        }
        return;
    }
    int z = (bid - 512) * 4096 + t * 16;
    #pragma unroll
    for (int j = 0; j < 4; j++)
        *(float4*)(g_psum + z + j * 4) = make_float4(0.f, 0.f, 0.f, 0.f);
    if (bid == 512 && t < 8) g_cnt[t] = 0.f;
}

// ---------------- K2: masked proto sum, latency-parallel ----------------
// grid (313, 8): block handles 8 rows; all row loads independent (full MLP).
__global__ void proto2_k(const float* __restrict__ s_f, const float* __restrict__ s_y) {
    const int b = blockIdx.y;
    const int n0 = blockIdx.x * 8;
    const int t = threadIdx.x;
    const float* sy = s_y + (size_t)b * 160000;
    float4 acc = make_float4(0.f, 0.f, 0.f, 0.f);
    int cnt = 0;
    #pragma unroll
    for (int j = 0; j < 8; j++) {
        int n = n0 + j;
        if (n < 2500) {
            float m = sy[(n / 50) * 3200 + (n % 50) * 8];   // nearest-neighbor stride-8
            if (m == 1.0f) {
                float4 v = *(const float4*)(s_f + (size_t)(b * 2500 + n) * 1024 + t * 4);
                acc.x += v.x; acc.y += v.y; acc.z += v.z; acc.w += v.w;
                cnt++;
            }
        }
    }
    if (cnt > 0) {
        float* ps = g_psum + b * 1024 + t * 4;
        atomicAdd(ps + 0, acc.x); atomicAdd(ps + 1, acc.y);
        atomicAdd(ps + 2, acc.z); atomicAdd(ps + 3, acc.w);
        if (t == 0) atomicAdd(&g_cnt[b], (float)cnt);
    }
}

// ---------------- K3: prototype selection (grid 8 = one CTA per batch) ----------------
__global__ void select3_k(const float* __restrict__ P) {   // P: [1024][16]
    __shared__ float s_sim[16], s_n2[16];
    __shared__ int   ssel;
    __shared__ float sfac;
    const int b = blockIdx.x, t = threadIdx.x, lane = t & 31, w = t >> 5;
    const float* ps = g_psum + b * 1024;
    for (int c = w; c < 16; c += 8) {
        float sd = 0.f, sn = 0.f;
        for (int d = lane; d < 1024; d += 32) {
            float pv = P[d * 16 + c];
            sd = fmaf(ps[d], pv, sd);
            sn = fmaf(pv, pv, sn);
        }
        #pragma unroll
        for (int o = 16; o; o >>= 1) {
            sd += __shfl_xor_sync(0xFFFFFFFFu, sd, o);
            sn += __shfl_xor_sync(0xFFFFFFFFu, sn, o);
        }
        if (!lane) { s_sim[c] = sd; s_n2[c] = sn; }
    }
    __syncthreads();
    if (t == 0) {
        int best = 0; float bv = -1e30f;
        #pragma unroll
        for (int c = 0; c < 16; c++) {
            float v = s_sim[c] * rsqrtf(fmaxf(s_n2[c], 1e-24f));
            if (v > bv) { bv = v; best = c; }
        }
        ssel = best;
        float sign = (g_cnt[b] > 0.5f) ? 1.0f : 0.0f;
        sfac = sign * 32.0f * rsqrtf(fmaxf(s_n2[best], 1e-24f));
    }
    __syncthreads();
    const int sel = ssel; const float fac = sfac;
    #pragma unroll
    for (int i = 0; i < 4; i++) {
        int d = t + i * 256;
        g_pvec[b * 1024 + d] = P[d * 16 + sel] * fac;
    }
}

// ---------------- K4: convert features to fp16 + per-row enhance scalar ----------------
__global__ void convert_k(const float* __restrict__ x, const float* __restrict__ s_f) {
    const int r = blockIdx.x * 8 + (threadIdx.x >> 5);
    const int lane = threadIdx.x & 31;
    __half* dst = g_fh + (size_t)r * 1024;
    if (r < ROWS_TOT) {
        const float* src = (r < ROWS_SF) ? s_f + (size_t)r * 1024
                                         : x + (size_t)(r - ROWS_SF) * 1024;
        const int bb = (r < ROWS_SF) ? r / 2500 : (r - ROWS_SF) / 2500;
        const float* pv = g_pvec + bb * 1024;
        float sq = 0.f, dp = 0.f;
        #pragma unroll
        for (int i = 0; i < 8; i++) {
            int c = i * 128 + lane * 4;
            float4 f = *(const float4*)(src + c);
            float4 p = *(const float4*)(pv + c);
            sq = fmaf(f.x, f.x, fmaf(f.y, f.y, fmaf(f.z, f.z, fmaf(f.w, f.w, sq))));
            dp = fmaf(f.x, p.x, fmaf(f.y, p.y, fmaf(f.z, p.z, fmaf(f.w, p.w, dp))));
            *(uint2*)(dst + c) = make_uint2(pkh2(f.x, f.y), pkh2(f.z, f.w));
        }
        #pragma unroll
        for (int o = 16; o; o >>= 1) {
            sq += __shfl_xor_sync(0xFFFFFFFFu, sq, o);
            dp += __shfl_xor_sync(0xFFFFFFFFu, dp, o);
        }
        if (!lane) {
            float g = fminf(fmaxf(dp / fmaxf(sqrtf(sq), 1e-12f), 0.0f), 6.0f);
            g_a[r] = 1.0f + g;
        }
    } else {
        #pragma unroll
        for (int i = 0; i < 8; i++)
            *(uint2*)(dst + i * 128 + lane * 4) = make_uint2(0u, 0u);
        if (!lane) g_a[r] = 1.0f;
    }
}

// ================= K5: fused down+up GEMM, BM=128, 3-stage cp.async pipeline =================
// grid 313, 256 thr = 8 warps (4 warpM x 2 warpN). Occupancy 2.
// smem bytes: A stages 3x18432 [0,55296); B stages 3x9216 [55296,82944); sA [82944,83456)
// Row stride 144 B => conflict-free stores and ldmatrix.
#define A_STG 18432u
#define B_BASE 55296u
#define B_STG 9216u
#define SM_BYTES 83456
extern __shared__ uint32_t smw[];

__global__ void __launch_bounds__(256, 2)
fused4_k(const float* __restrict__ bdn, const float* __restrict__ bup,
         float* __restrict__ out) {
    uint32_t* Aw0 = smw;
    float*    sA  = (float*)(smw + 20736);   // 82944/4

    const uint32_t sbase = smem_u32(smw);
    const int t = threadIdx.x, wid = t >> 5, lane = t & 31;
    const int warpM = wid & 3, warpN = wid >> 2;
    const int row0 = blockIdx.x * 128;

    // ldmatrix per-lane base addresses (byte), stage 0
    const int lr16 = lane & 15, lk16 = (lane >> 4) & 1;
    const uint32_t aAddr0 = sbase + (uint32_t)((warpM * 32 + lr16) * 144 + lk16 * 16);
    const int brr = warpN * 32 + ((lane >> 4) & 1) * 8 + (lane & 7);
    const uint32_t bAddr0 = sbase + B_BASE + (uint32_t)(brr * 144 + ((lane >> 3) & 1) * 16);

    // cp.async segment mapping: A 1024 segs (4/thread), B 512 segs (2/thread)
    const int an0 = t >> 3, aq = t & 7;
    const uint32_t adst = sbase + (uint32_t)(an0 * 144 + aq * 16);
    const int bn0 = t >> 3;
    const uint32_t bdst = sbase + B_BASE + (uint32_t)(bn0 * 144 + aq * 16);
    const __half* asrc = g_fh + (size_t)(row0 + an0) * 1024 + aq * 8;

    if (t < 128) sA[t] = g_a[row0 + t];

    float acc[8][4];
    #pragma unroll
    for (int i = 0; i < 8; i++)
        #pragma unroll
        for (int j = 0; j < 4; j++) acc[i][j] = 0.f;

    // ---- prologue: chunks 0,1 into stages 0,1 ----
    #pragma unroll
    for (int cc = 0; cc < 2; cc++) {
        const __half* as = asrc + cc * 64;
        const __half* bs = g_wd + cc * 4096 + bn0 * 64 + aq * 8;
        #pragma unroll
        for (int j = 0; j < 4; j++)
            cpasync16(adst + (uint32_t)cc * A_STG + (uint32_t)(j * 32) * 144,
                      as + (size_t)(j * 32) * 1024);
        #pragma unroll
        for (int j = 0; j < 2; j++)
            cpasync16(bdst + (uint32_t)cc * B_STG + (uint32_t)(j * 32) * 144, bs + j * 32 * 64);
        cp_commit();
    }
    cp_wait1();     // chunk 0 complete
    __syncthreads();

    // ============ down phase: 16 chunks of 64, 3-stage, distance-2 prefetch ============
    #pragma unroll 1
    for (int c = 0; c < 16; c++) {
        const uint32_t cur = (uint32_t)(c % 3);
        if (c + 2 < 16) {
            const uint32_t stg = (uint32_t)((c + 2) % 3);
            const __half* as = asrc + (c + 2) * 64;
            const __half* bs = g_wd + (c + 2) * 4096 + bn0 * 64 + aq * 8;
            #pragma unroll
            for (int j = 0; j < 4; j++)
                cpasync16(adst + stg * A_STG + (uint32_t)(j * 32) * 144,
                          as + (size_t)(j * 32) * 1024);
            #pragma unroll
            for (int j = 0; j < 2; j++)
                cpasync16(bdst + stg * B_STG + (uint32_t)(j * 32) * 144, bs + j * 32 * 64);
            cp_commit();
        }
        {
            const uint32_t aA = aAddr0 + cur * A_STG;
            const uint32_t bA = bAddr0 + cur * B_STG;
            #pragma unroll
            for (int ks = 0; ks < 4; ks++) {
                uint32_t af[2][4], bf[2][4];
                ldsm_x4(aA + ks * 32, af[0]);
                ldsm_x4(aA + 16 * 144 + ks * 32, af[1]);
                ldsm_x4(bA + ks * 32, bf[0]);
                ldsm_x4(bA + 16 * 144 + ks * 32, bf[1]);
                #pragma unroll
                for (int mt = 0; mt < 2; mt++)
                    #pragma unroll
                    for (int nt = 0; nt < 4; nt++) {
                        const int n2 = nt >> 1, s = (nt & 1) * 2;
                        mma_f16(acc[mt * 4 + nt], af[mt][0], af[mt][1], af[mt][2], af[mt][3],
                                bf[n2][s], bf[n2][s + 1]);
                    }
            }
        }
        if (c + 2 < 16) cp_wait1(); else cp_wait0();   // chunk c+1 complete
        __syncthreads();
    }

    // prefetch up-phase chunks 0,1 of B into B stages 0,1
    #pragma unroll
    for (int cc = 0; cc < 2; cc++) {
        const __half* bs = g_wu + cc * 4096 + bn0 * 64 + aq * 8;
        #pragma unroll
        for (int j = 0; j < 2; j++)
            cpasync16(bdst + (uint32_t)cc * B_STG + (uint32_t)(j * 32) * 144, bs + j * 32 * 64);
        cp_commit();
    }

    // ---- down epilogue: h = relu(a*dot + b_down) -> fp16 into A stage-0 plane ----
    #pragma unroll
    for (int nt = 0; nt < 4; nt++) {
        const int c0 = warpN * 32 + nt * 8 + (lane & 3) * 2;
        const float bd0 = __ldg(bdn + c0), bd1 = __ldg(bdn + c0 + 1);
        #pragma unroll
        for (int mt = 0; mt < 2; mt++) {
            const float* d = acc[mt * 4 + nt];
            const int rb = warpM * 32 + mt * 16 + (lane >> 2);
            #pragma unroll
            for (int rr = 0; rr < 2; rr++) {
                const int rloc = rb + rr * 8;
                float av2 = sA[rloc];
                float h0 = fmaxf(fmaf(av2, d[rr * 2 + 0], bd0), 0.f);
                float h1 = fmaxf(fmaf(av2, d[rr * 2 + 1], bd1), 0.f);
                Aw0[rloc * 36 + c0 / 2] = pkh2(h0, h1);
            }
        }
    }
    cp_wait1();      // up-B0 complete
    __syncthreads(); // h + up-B0 visible

    // hoist up-phase A (h) fragments: invariant across all 16 N-chunks
    uint32_t afh[4][2][4];
    #pragma unroll
    for (int ks = 0; ks < 4; ks++) {
        ldsm_x4(aAddr0 + ks * 32, afh[ks][0]);
        ldsm_x4(aAddr0 + 16 * 144 + ks * 32, afh[ks][1]);
    }

    // ============ up phase: 16 N-chunks of 64, A = h (regs), B 3-stage ============
    #pragma unroll 1
    for (int nc = 0; nc < 16; nc++) {
        const uint32_t cur = (uint32_t)(nc % 3);
        if (nc + 2 < 16) {
            const uint32_t stg = (uint32_t)((nc + 2) % 3);
            const __half* bs = g_wu + (nc + 2) * 4096 + bn0 * 64 + aq * 8;
            #pragma unroll
            for (int j = 0; j < 2; j++)
                cpasync16(bdst + stg * B_STG + (uint32_t)(j * 32) * 144, bs + j * 32 * 64);
            cp_commit();
        }
        #pragma unroll
        for (int i = 0; i < 8; i++)
            #pragma unroll
            for (int j = 0; j < 4; j++) acc[i][j] = 0.f;
        {
            const uint32_t bA = bAddr0 + cur * B_STG;
            #pragma unroll
            for (int ks = 0; ks < 4; ks++) {
                uint32_t bf[2][4];
                ldsm_x4(bA + ks * 32, bf[0]);
                ldsm_x4(bA + 16 * 144 + ks * 32, bf[1]);
                #pragma unroll
                for (int mt = 0; mt < 2; mt++)
                    #pragma unroll
                    for (int nt = 0; nt < 4; nt++) {
                        const int n2 = nt >> 1, s = (nt & 1) * 2;
                        mma_f16(acc[mt * 4 + nt], afh[ks][mt][0], afh[ks][mt][1],
                                afh[ks][mt][2], afh[ks][mt][3], bf[n2][s], bf[n2][s + 1]);
                    }
            }
        }
        // epilogue: out = acc + b_up
        const int nb64 = nc * 64;
        #pragma unroll
        for (int nt = 0; nt < 4; nt++) {
            const int c0 = warpN * 32 + nt * 8 + (lane & 3) * 2;
            const float u0 = __ldg(bup + nb64 + c0), u1 = __ldg(bup + nb64 + c0 + 1);
            #pragma unroll
            for (int mt = 0; mt < 2; mt++) {
                const float* d = acc[mt * 4 + nt];
                const int rb = warpM * 32 + mt * 16 + (lane >> 2);
                #pragma unroll
                for (int rr = 0; rr < 2; rr++) {
                    int row = row0 + rb + rr * 8;
                    if (row < ROWS_TOT) {
                        float2 v = make_float2(d[rr * 2 + 0] + u0, d[rr * 2 + 1] + u1);
                        *(float2*)(out + (size_t)row * 1024 + nb64 + c0) = v;
                    }
                }
            }
        }
        if (nc + 2 < 16) cp_wait1(); else cp_wait0();
        __syncthreads();
    }
}

// ---------------- launch ----------------
extern "C" void kernel_launch(void* const* d_in, const int* in_sizes, int n_in,
                              void* d_out, int out_size) {
    (void)in_sizes; (void)n_in; (void)out_size;
    const float* x   = (const float*)d_in[0];
    const float* s_f = (const float*)d_in[1];
    const float* s_y = (const float*)d_in[2];
    const float* P   = (const float*)d_in[3];
    const float* Wd  = (const float*)d_in[4];
    const float* bd  = (const float*)d_in[5];
    const float* Wu  = (const float*)d_in[6];
    const float* bu  = (const float*)d_in[7];
    float* out = (float*)d_out;

    static bool attr_set = false;
    if (!attr_set) {
        cudaFuncSetAttribute(fused4_k, cudaFuncAttributeMaxDynamicSharedMemorySize, SM_BYTES);
        attr_set = true;
    }

    prep_all_k<<<514, 256>>>(Wd, Wu);
    proto2_k<<<dim3(313, 8), 256>>>(s_f, s_y);
    select3_k<<<8, 256>>>(P);
    convert_k<<<5008, 256>>>(x, s_f);
    fused4_k<<<313, 256, SM_BYTES>>>(bd, bu, out);
}

// round 15
// speedup vs baseline: 1.0840x; 1.0104x over previous
#include <cuda_runtime.h>
#include <cuda_fp16.h>
#include <cstdint>

#define ROWS_TOT 40000
#define ROWS_SF  20000
#define ROWS_PAD 40064        // 313 * 128

// ---------------- scratch (static device globals; no runtime allocation) ----------------
__device__ float g_psum[8 * 1024];
__device__ float g_cnt[8];
__device__ float g_pvec[8 * 1024];
__device__ float g_a[ROWS_PAD];
__device__ __align__(16) __half g_fh[(size_t)ROWS_PAD * 1024];   // pre-converted features
__device__ __align__(16) __half g_wd[16 * 64 * 64];   // [chunk][n][k] fp16
__device__ __align__(16) __half g_wu[1024 * 64];      // [n][k] fp16 (chunk = n/64)

// ---------------- helpers ----------------
__device__ __forceinline__ void mma_f16(float* d, uint32_t a0, uint32_t a1, uint32_t a2,
                                        uint32_t a3, uint32_t b0, uint32_t b1) {
    asm volatile(
        "mma.sync.aligned.m16n8k16.row.col.f32.f16.f16.f32 "
        "{%0,%1,%2,%3}, {%4,%5,%6,%7}, {%8,%9}, {%0,%1,%2,%3};"
        : "+f"(d[0]), "+f"(d[1]), "+f"(d[2]), "+f"(d[3])
        : "r"(a0), "r"(a1), "r"(a2), "r"(a3), "r"(b0), "r"(b1));
}
__device__ __forceinline__ void ldsm_x4(uint32_t addr, uint32_t* r) {
    asm volatile("ldmatrix.sync.aligned.m8n8.x4.shared.b16 {%0,%1,%2,%3}, [%4];"
                 : "=r"(r[0]), "=r"(r[1]), "=r"(r[2]), "=r"(r[3]) : "r"(addr));
}
__device__ __forceinline__ uint32_t smem_u32(const void* p) {
    uint32_t a;
    asm("{ .reg .u64 t; cvta.to.shared.u64 t, %1; cvt.u32.u64 %0, t; }" : "=r"(a) : "l"(p));
    return a;
}
__device__ __forceinline__ uint32_t pkh2(float x, float y) {
    __half2 h = __float22half2_rn(make_float2(x, y));
    return *reinterpret_cast<uint32_t*>(&h);
}
__device__ __forceinline__ void cpasync16(uint32_t saddr, const void* gaddr) {
    asm volatile("cp.async.cg.shared.global [%0], [%1], 16;" :: "r"(saddr), "l"(gaddr));
}
__device__ __forceinline__ void cp_commit() {
    asm volatile("cp.async.commit_group;");
}
__device__ __forceinline__ void cp_wait0() {
    asm volatile("cp.async.wait_group 0;");
}

// ---------------- K1: weight prep + zero accumulators ----------------
// grid 514: [0,512) weights; 512,513 zero g_psum/g_cnt.
__global__ void prep_all_k(const float* __restrict__ Wd, const float* __restrict__ Wu) {
    const int bid = blockIdx.x, t = threadIdx.x;
    if (bid < 512) {
        int i = bid * 256 + t;
        if (i < 65536) {                       // Wd [64][1024] -> chunked [16][64][64]
            int n = i >> 10, kk = i & 1023;
            int c = kk >> 6, k = kk & 63;
            g_wd[c * 4096 + n * 64 + k] = __float2half_rn(Wd[i]);
        } else {                               // Wu [1024][64]
            int j = i - 65536;
            g_wu[j] = __float2half_rn(Wu[j]);
        }
        return;
    }
    int z = (bid - 512) * 4096 + t * 16;
    #pragma unroll
    for (int j = 0; j < 4; j++)
        *(float4*)(g_psum + z + j * 4) = make_float4(0.f, 0.f, 0.f, 0.f);
    if (bid == 512 && t < 8) g_cnt[t] = 0.f;
}

// ---------------- K2: masked proto sum, latency-parallel ----------------
// grid (313, 8): block handles 8 rows; all row loads independent (full MLP).
__global__ void proto2_k(const float* __restrict__ s_f, const float* __restrict__ s_y) {
    const int b = blockIdx.y;
    const int n0 = blockIdx.x * 8;
    const int t = threadIdx.x;
    const float* sy = s_y + (size_t)b * 160000;
    float4 acc = make_float4(0.f, 0.f, 0.f, 0.f);
    int cnt = 0;
    #pragma unroll
    for (int j = 0; j < 8; j++) {
        int n = n0 + j;
        if (n < 2500) {
            float m = sy[(n / 50) * 3200 + (n % 50) * 8];   // nearest-neighbor stride-8
            if (m == 1.0f) {
                float4 v = *(const float4*)(s_f + (size_t)(b * 2500 + n) * 1024 + t * 4);
                acc.x += v.x; acc.y += v.y; acc.z += v.z; acc.w += v.w;
                cnt++;
            }
        }
    }
    if (cnt > 0) {
        float* ps = g_psum + b * 1024 + t * 4;
        atomicAdd(ps + 0, acc.x); atomicAdd(ps + 1, acc.y);
        atomicAdd(ps + 2, acc.z); atomicAdd(ps + 3, acc.w);
        if (t == 0) atomicAdd(&g_cnt[b], (float)cnt);
    }
}

// ---------------- K3: prototype selection (grid 8 = one CTA per batch) ----------------
__global__ void select3_k(const float* __restrict__ P) {   // P: [1024][16]
    __shared__ float s_sim[16], s_n2[16];
    __shared__ int   ssel;
    __shared__ float sfac;
    const int b = blockIdx.x, t = threadIdx.x, lane = t & 31, w = t >> 5;
    const float* ps = g_psum + b * 1024;
    for (int c = w; c < 16; c += 8) {
        float sd = 0.f, sn = 0.f;
        for (int d = lane; d < 1024; d += 32) {
            float pv = P[d * 16 + c];
            sd = fmaf(ps[d], pv, sd);
            sn = fmaf(pv, pv, sn);
        }
        #pragma unroll
        for (int o = 16; o; o >>= 1) {
            sd += __shfl_xor_sync(0xFFFFFFFFu, sd, o);
            sn += __shfl_xor_sync(0xFFFFFFFFu, sn, o);
        }
        if (!lane) { s_sim[c] = sd; s_n2[c] = sn; }
    }
    __syncthreads();
    if (t == 0) {
        int best = 0; float bv = -1e30f;
        #pragma unroll
        for (int c = 0; c < 16; c++) {
            float v = s_sim[c] * rsqrtf(fmaxf(s_n2[c], 1e-24f));
            if (v > bv) { bv = v; best = c; }
        }
        ssel = best;
        float sign = (g_cnt[b] > 0.5f) ? 1.0f : 0.0f;
        sfac = sign * 32.0f * rsqrtf(fmaxf(s_n2[best], 1e-24f));
    }
    __syncthreads();
    const int sel = ssel; const float fac = sfac;
    #pragma unroll
    for (int i = 0; i < 4; i++) {
        int d = t + i * 256;
        g_pvec[b * 1024 + d] = P[d * 16 + sel] * fac;
    }
}

// ---------------- K4: convert features to fp16 + per-row enhance scalar ----------------
__global__ void convert_k(const float* __restrict__ x, const float* __restrict__ s_f) {
    const int r = blockIdx.x * 8 + (threadIdx.x >> 5);
    const int lane = threadIdx.x & 31;
    __half* dst = g_fh + (size_t)r * 1024;
    if (r < ROWS_TOT) {
        const float* src = (r < ROWS_SF) ? s_f + (size_t)r * 1024
                                         : x + (size_t)(r - ROWS_SF) * 1024;
        const int bb = (r < ROWS_SF) ? r / 2500 : (r - ROWS_SF) / 2500;
        const float* pv = g_pvec + bb * 1024;
        float sq = 0.f, dp = 0.f;
        #pragma unroll
        for (int i = 0; i < 8; i++) {
            int c = i * 128 + lane * 4;
            float4 f = *(const float4*)(src + c);
            float4 p = *(const float4*)(pv + c);
            sq = fmaf(f.x, f.x, fmaf(f.y, f.y, fmaf(f.z, f.z, fmaf(f.w, f.w, sq))));
            dp = fmaf(f.x, p.x, fmaf(f.y, p.y, fmaf(f.z, p.z, fmaf(f.w, p.w, dp))));
            *(uint2*)(dst + c) = make_uint2(pkh2(f.x, f.y), pkh2(f.z, f.w));
        }
        #pragma unroll
        for (int o = 16; o; o >>= 1) {
            sq += __shfl_xor_sync(0xFFFFFFFFu, sq, o);
            dp += __shfl_xor_sync(0xFFFFFFFFu, dp, o);
        }
        if (!lane) {
            float g = fminf(fmaxf(dp / fmaxf(sqrtf(sq), 1e-12f), 0.0f), 6.0f);
            g_a[r] = 1.0f + g;
        }
    } else {
        #pragma unroll
        for (int i = 0; i < 8; i++)
            *(uint2*)(dst + i * 128 + lane * 4) = make_uint2(0u, 0u);
        if (!lane) g_a[r] = 1.0f;
    }
}

// ================= K5: fused down GEMM + up GEMM (R12 config: measured 79.1 us) ==========
// grid 313, BM=128. 256 thr = 8 warps (4 warpM x 2 warpN). Occupancy 3.
// smem byte layout (double buffered):
//   A0[0,18432) A1[18432,36864) B0[36864,46080) B1[46080,55296) sA[55296,55808)
// Row stride 144 B => conflict-free stores and ldmatrix.
#define SM_BYTES 55808
extern __shared__ uint32_t smw[];

__global__ void __launch_bounds__(256, 3)
fused2_k(const float* __restrict__ bdn, const float* __restrict__ bup,
         float* __restrict__ out) {
    uint32_t* Aw0 = smw;
    float*    sA  = (float*)(smw + 13824);

    const uint32_t sbase = smem_u32(smw);
    const int t = threadIdx.x, wid = t >> 5, lane = t & 31;
    const int warpM = wid & 3, warpN = wid >> 2;
    const int row0 = blockIdx.x * 128;

    // ldmatrix per-lane base addresses (byte), stage 0
    const int lr16 = lane & 15, lk16 = (lane >> 4) & 1;
    const uint32_t aAddr0 = sbase + (uint32_t)((warpM * 32 + lr16) * 144 + lk16 * 16);
    const int brr = warpN * 32 + ((lane >> 4) & 1) * 8 + (lane & 7);
    const uint32_t bAddr0 = sbase + 36864 + (uint32_t)(brr * 144 + ((lane >> 3) & 1) * 16);

    // cp.async segment mapping
    const int an0 = t >> 3, aq = t & 7;
    const uint32_t adst = sbase + (uint32_t)(an0 * 144 + aq * 16);
    const int bn0 = t >> 3;
    const uint32_t bdst = sbase + 36864 + (uint32_t)(bn0 * 144 + aq * 16);
    const __half* asrc = g_fh + (size_t)(row0 + an0) * 1024 + aq * 8;

    if (t < 128) sA[t] = g_a[row0 + t];

    float acc[8][4];
    #pragma unroll
    for (int i = 0; i < 8; i++)
        #pragma unroll
        for (int j = 0; j < 4; j++) acc[i][j] = 0.f;

    // ---- prologue: chunk 0 into stage 0 ----
    #pragma unroll
    for (int j = 0; j < 4; j++)
        cpasync16(adst + (uint32_t)(j * 32) * 144, asrc + (size_t)(j * 32) * 1024);
    #pragma unroll
    for (int j = 0; j < 2; j++)
        cpasync16(bdst + (uint32_t)(j * 32) * 144, g_wd + (bn0 + j * 32) * 64 + aq * 8);
    cp_commit();
    cp_wait0();
    __syncthreads();

    // ============ down phase: 16 chunks of 64, double-buffered ============
    #pragma unroll 1
    for (int c = 0; c < 16; c++) {
        const uint32_t cur = (uint32_t)(c & 1), nxt = cur ^ 1u;
        if (c < 15) {
            const __half* as = asrc + (c + 1) * 64;
            const __half* bs = g_wd + (c + 1) * 4096 + bn0 * 64 + aq * 8;
            #pragma unroll
            for (int j = 0; j < 4; j++)
                cpasync16(adst + nxt * 18432u + (uint32_t)(j * 32) * 144, as + (size_t)(j * 32) * 1024);
            #pragma unroll
            for (int j = 0; j < 2; j++)
                cpasync16(bdst + nxt * 9216u + (uint32_t)(j * 32) * 144, bs + j * 32 * 64);
            cp_commit();
        }
        {
            const uint32_t aA = aAddr0 + cur * 18432u;
            const uint32_t bA = bAddr0 + cur * 9216u;
            #pragma unroll
            for (int ks = 0; ks < 4; ks++) {
                uint32_t af[2][4], bf[2][4];
                ldsm_x4(aA + ks * 32, af[0]);
                ldsm_x4(aA + 16 * 144 + ks * 32, af[1]);
                ldsm_x4(bA + ks * 32, bf[0]);
                ldsm_x4(bA + 16 * 144 + ks * 32, bf[1]);
                #pragma unroll
                for (int mt = 0; mt < 2; mt++)
                    #pragma unroll
                    for (int nt = 0; nt < 4; nt++) {
                        const int n2 = nt >> 1, s = (nt & 1) * 2;
                        mma_f16(acc[mt * 4 + nt], af[mt][0], af[mt][1], af[mt][2], af[mt][3],
                                bf[n2][s], bf[n2][s + 1]);
                    }
            }
        }
        cp_wait0();
        __syncthreads();
    }

    // prefetch up-phase chunk 0 B into stage 0 (B planes free)
    #pragma unroll
    for (int j = 0; j < 2; j++)
        cpasync16(bdst + (uint32_t)(j * 32) * 144, g_wu + (bn0 + j * 32) * 64 + aq * 8);
    cp_commit();

    // ---- down epilogue: h = relu(a*dot + b_down) -> fp16 into A stage-0 plane ----
    #pragma unroll
    for (int nt = 0; nt < 4; nt++) {
        const int c0 = warpN * 32 + nt * 8 + (lane & 3) * 2;
        const float bd0 = __ldg(bdn + c0), bd1 = __ldg(bdn + c0 + 1);
        #pragma unroll
        for (int mt = 0; mt < 2; mt++) {
            const float* d = acc[mt * 4 + nt];
            const int rb = warpM * 32 + mt * 16 + (lane >> 2);
            #pragma unroll
            for (int rr = 0; rr < 2; rr++) {
                const int rloc = rb + rr * 8;
                float av2 = sA[rloc];
                float h0 = fmaxf(fmaf(av2, d[rr * 2 + 0], bd0), 0.f);
                float h1 = fmaxf(fmaf(av2, d[rr * 2 + 1], bd1), 0.f);
                Aw0[rloc * 36 + c0 / 2] = pkh2(h0, h1);
            }
        }
    }
    cp_wait0();
    __syncthreads();   // h visible, up-B0 loaded

    // hoist up-phase A (h) fragments: invariant across all 16 N-chunks
    uint32_t afh[4][2][4];
    #pragma unroll
    for (int ks = 0; ks < 4; ks++) {
        ldsm_x4(aAddr0 + ks * 32, afh[ks][0]);
        ldsm_x4(aAddr0 + 16 * 144 + ks * 32, afh[ks][1]);
    }

    // ============ up phase: 16 N-chunks of 64, A = h (regs), B double-buffered ============
    #pragma unroll 1
    for (int nc = 0; nc < 16; nc++) {
        const uint32_t cur = (uint32_t)(nc & 1);
        if (nc < 15) {
            const __half* bs = g_wu + (nc + 1) * 4096 + bn0 * 64 + aq * 8;
            const uint32_t bo = (cur ^ 1u) * 9216u;
            #pragma unroll
            for (int j = 0; j < 2; j++)
                cpasync16(bdst + bo + (uint32_t)(j * 32) * 144, bs + j * 32 * 64);
            cp_commit();
        }
        #pragma unroll
        for (int i = 0; i < 8; i++)
            #pragma unroll
            for (int j = 0; j < 4; j++) acc[i][j] = 0.f;
        {
            const uint32_t bA = bAddr0 + cur * 9216u;
            #pragma unroll
            for (int ks = 0; ks < 4; ks++) {
                uint32_t bf[2][4];
                ldsm_x4(bA + ks * 32, bf[0]);
                ldsm_x4(bA + 16 * 144 + ks * 32, bf[1]);
                #pragma unroll
                for (int mt = 0; mt < 2; mt++)
                    #pragma unroll
                    for (int nt = 0; nt < 4; nt++) {
                        const int n2 = nt >> 1, s = (nt & 1) * 2;
                        mma_f16(acc[mt * 4 + nt], afh[ks][mt][0], afh[ks][mt][1],
                                afh[ks][mt][2], afh[ks][mt][3], bf[n2][s], bf[n2][s + 1]);
                    }
            }
        }
        // epilogue: out = acc + b_up
        const int nb64 = nc * 64;
        #pragma unroll
        for (int nt = 0; nt < 4; nt++) {
            const int c0 = warpN * 32 + nt * 8 + (lane & 3) * 2;
            const float u0 = __ldg(bup + nb64 + c0), u1 = __ldg(bup + nb64 + c0 + 1);
            #pragma unroll
            for (int mt = 0; mt < 2; mt++) {
                const float* d = acc[mt * 4 + nt];
                const int rb = warpM * 32 + mt * 16 + (lane >> 2);
                #pragma unroll
                for (int rr = 0; rr < 2; rr++) {
                    int row = row0 + rb + rr * 8;
                    if (row < ROWS_TOT) {
                        float2 v = make_float2(d[rr * 2 + 0] + u0, d[rr * 2 + 1] + u1);
                        *(float2*)(out + (size_t)row * 1024 + nb64 + c0) = v;
                    }
                }
            }
        }
        cp_wait0();
        __syncthreads();
    }
}

// ---------------- launch ----------------
extern "C" void kernel_launch(void* const* d_in, const int* in_sizes, int n_in,
                              void* d_out, int out_size) {
    (void)in_sizes; (void)n_in; (void)out_size;
    const float* x   = (const float*)d_in[0];
    const float* s_f = (const float*)d_in[1];
    const float* s_y = (const float*)d_in[2];
    const float* P   = (const float*)d_in[3];
    const float* Wd  = (const float*)d_in[4];
    const float* bd  = (const float*)d_in[5];
    const float* Wu  = (const float*)d_in[6];
    const float* bu  = (const float*)d_in[7];
    float* out = (float*)d_out;

    static bool attr_set = false;
    if (!attr_set) {
        cudaFuncSetAttribute(fused2_k, cudaFuncAttributeMaxDynamicSharedMemorySize, SM_BYTES);
        attr_set = true;
    }

    prep_all_k<<<514, 256>>>(Wd, Wu);
    proto2_k<<<dim3(313, 8), 256>>>(s_f, s_y);
    select3_k<<<8, 256>>>(P);
    convert_k<<<5008, 256>>>(x, s_f);
    fused2_k<<<313, 256, SM_BYTES>>>(bd, bu, out);
}

// round 16
// speedup vs baseline: 1.2527x; 1.1556x over previous
#include <cuda_runtime.h>
#include <cuda_fp16.h>
#include <cstdint>

#define ROWS_TOT 40000
#define ROWS_SF  20000
#define ROWS_PAD 40032        // 417 * 96

// ---------------- scratch (static device globals; no runtime allocation) ----------------
__device__ float g_psum_p[256 * 1024];   // 32 partial slots per batch, written unconditionally
__device__ float g_cnt_p[256];
__device__ float g_pvec[8 * 1024];
__device__ float g_a[ROWS_PAD];
__device__ __align__(16) __half g_fh[(size_t)ROWS_PAD * 1024];   // pre-converted features
__device__ __align__(16) __half g_wd[16 * 64 * 64];   // [chunk][n][k] fp16
__device__ __align__(16) __half g_wu[1024 * 64];      // [n][k] fp16 (chunk = n/64)

// ---------------- helpers ----------------
__device__ __forceinline__ void mma_f16(float* d, uint32_t a0, uint32_t a1, uint32_t a2,
                                        uint32_t a3, uint32_t b0, uint32_t b1) {
    asm volatile(
        "mma.sync.aligned.m16n8k16.row.col.f32.f16.f16.f32 "
        "{%0,%1,%2,%3}, {%4,%5,%6,%7}, {%8,%9}, {%0,%1,%2,%3};"
        : "+f"(d[0]), "+f"(d[1]), "+f"(d[2]), "+f"(d[3])
        : "r"(a0), "r"(a1), "r"(a2), "r"(a3), "r"(b0), "r"(b1));
}
__device__ __forceinline__ void ldsm_x4(uint32_t addr, uint32_t* r) {
    asm volatile("ldmatrix.sync.aligned.m8n8.x4.shared.b16 {%0,%1,%2,%3}, [%4];"
                 : "=r"(r[0]), "=r"(r[1]), "=r"(r[2]), "=r"(r[3]) : "r"(addr));
}
__device__ __forceinline__ uint32_t smem_u32(const void* p) {
    uint32_t a;
    asm("{ .reg .u64 t; cvta.to.shared.u64 t, %1; cvt.u32.u64 %0, t; }" : "=r"(a) : "l"(p));
    return a;
}
__device__ __forceinline__ uint32_t pkh2(float x, float y) {
    __half2 h = __float22half2_rn(make_float2(x, y));
    return *reinterpret_cast<uint32_t*>(&h);
}
__device__ __forceinline__ void cpasync16(uint32_t saddr, const void* gaddr) {
    asm volatile("cp.async.cg.shared.global [%0], [%1], 16;" :: "r"(saddr), "l"(gaddr));
}
__device__ __forceinline__ void cp_commit() {
    asm volatile("cp.async.commit_group;");
}
__device__ __forceinline__ void cp_wait0() {
    asm volatile("cp.async.wait_group 0;");
}

// ---------------- K1: weight prep + proto partial sums (no zeroing, no atomics) ---------
// grid 768: [0,512) weights; [512,768) proto partials (32 blocks x 8 batches).
__global__ void combo_k(const float* __restrict__ Wd, const float* __restrict__ Wu,
                        const float* __restrict__ s_f, const float* __restrict__ s_y) {
    const int bid = blockIdx.x, t = threadIdx.x;
    if (bid < 512) {
        int i = bid * 256 + t;
        if (i < 65536) {                       // Wd [64][1024] -> chunked [16][64][64]
            int n = i >> 10, kk = i & 1023;
            int c = kk >> 6, k = kk & 63;
            g_wd[c * 4096 + n * 64 + k] = __float2half_rn(Wd[i]);
        } else {                               // Wu [1024][64]
            int j = i - 65536;
            g_wu[j] = __float2half_rn(Wu[j]);
        }
        return;
    }
    const int p = bid - 512;                   // 0..255
    const int b = p >> 5, g = p & 31;
    const int n0 = g * 79;
    const int n1 = min(n0 + 79, 2500);
    const float* sy = s_y + (size_t)b * 160000;
    float4 acc = make_float4(0.f, 0.f, 0.f, 0.f);
    int cnt = 0;
    for (int n = n0; n < n1; n++) {
        float m = sy[(n / 50) * 3200 + (n % 50) * 8];   // nearest-neighbor stride-8
        if (m == 1.0f) {
            float4 v = *(const float4*)(s_f + (size_t)(b * 2500 + n) * 1024 + t * 4);
            acc.x += v.x; acc.y += v.y; acc.z += v.z; acc.w += v.w;
            cnt++;
        }
    }
    *(float4*)(g_psum_p + (size_t)p * 1024 + t * 4) = acc;   // unconditional: no zeroing needed
    if (t == 0) g_cnt_p[p] = (float)cnt;
}

// ---------------- K2: prototype selection (grid 8 = one CTA per batch) ----------------
__global__ void select3_k(const float* __restrict__ P) {   // P: [1024][16]
    __shared__ float psum[1024];
    __shared__ float s_sim[16], s_n2[16];
    __shared__ float scnt;
    __shared__ int   ssel;
    __shared__ float sfac;
    const int b = blockIdx.x, t = threadIdx.x, lane = t & 31, w = t >> 5;
    #pragma unroll
    for (int i = 0; i < 4; i++) {
        int d = t + i * 256;
        float s = 0.f;
        #pragma unroll
        for (int g = 0; g < 32; g++) s += g_psum_p[(size_t)(b * 32 + g) * 1024 + d];
        psum[d] = s;
    }
    if (t == 0) {
        float c = 0.f;
        #pragma unroll
        for (int g = 0; g < 32; g++) c += g_cnt_p[b * 32 + g];
        scnt = c;
    }
    __syncthreads();
    for (int c = w; c < 16; c += 8) {
        float sd = 0.f, sn = 0.f;
        for (int d = lane; d < 1024; d += 32) {
            float pv = P[d * 16 + c];
            sd = fmaf(psum[d], pv, sd);
            sn = fmaf(pv, pv, sn);
        }
        #pragma unroll
        for (int o = 16; o; o >>= 1) {
            sd += __shfl_xor_sync(0xFFFFFFFFu, sd, o);
            sn += __shfl_xor_sync(0xFFFFFFFFu, sn, o);
        }
        if (!lane) { s_sim[c] = sd; s_n2[c] = sn; }
    }
    __syncthreads();
    if (t == 0) {
        int best = 0; float bv = -1e30f;
        #pragma unroll
        for (int c = 0; c < 16; c++) {
            float v = s_sim[c] * rsqrtf(fmaxf(s_n2[c], 1e-24f));
            if (v > bv) { bv = v; best = c; }
        }
        ssel = best;
        float sign = (scnt > 0.5f) ? 1.0f : 0.0f;
        sfac = sign * 32.0f * rsqrtf(fmaxf(s_n2[best], 1e-24f));
    }
    __syncthreads();
    const int sel = ssel; const float fac = sfac;
    #pragma unroll
    for (int i = 0; i < 4; i++) {
        int d = t + i * 256;
        g_pvec[b * 1024 + d] = P[d * 16 + sel] * fac;
    }
}

// ---------------- K3: convert features to fp16 + per-row enhance scalar ----------------
__global__ void convert_k(const float* __restrict__ x, const float* __restrict__ s_f) {
    const int r = blockIdx.x * 8 + (threadIdx.x >> 5);
    const int lane = threadIdx.x & 31;
    __half* dst = g_fh + (size_t)r * 1024;
    if (r < ROWS_TOT) {
        const float* src = (r < ROWS_SF) ? s_f + (size_t)r * 1024
                                         : x + (size_t)(r - ROWS_SF) * 1024;
        const int bb = (r < ROWS_SF) ? r / 2500 : (r - ROWS_SF) / 2500;
        const float* pv = g_pvec + bb * 1024;
        float sq = 0.f, dp = 0.f;
        #pragma unroll
        for (int i = 0; i < 8; i++) {
            int c = i * 128 + lane * 4;
            float4 f = *(const float4*)(src + c);
            float4 p = *(const float4*)(pv + c);
            sq = fmaf(f.x, f.x, fmaf(f.y, f.y, fmaf(f.z, f.z, fmaf(f.w, f.w, sq))));
            dp = fmaf(f.x, p.x, fmaf(f.y, p.y, fmaf(f.z, p.z, fmaf(f.w, p.w, dp))));
            *(uint2*)(dst + c) = make_uint2(pkh2(f.x, f.y), pkh2(f.z, f.w));
        }
        #pragma unroll
        for (int o = 16; o; o >>= 1) {
            sq += __shfl_xor_sync(0xFFFFFFFFu, sq, o);
            dp += __shfl_xor_sync(0xFFFFFFFFu, dp, o);
        }
        if (!lane) {
            float g = fminf(fmaxf(dp / fmaxf(sqrtf(sq), 1e-12f), 0.0f), 6.0f);
            g_a[r] = 1.0f + g;
        }
    } else if (r < ROWS_PAD) {
        #pragma unroll
        for (int i = 0; i < 8; i++)
            *(uint2*)(dst + i * 128 + lane * 4) = make_uint2(0u, 0u);
        if (!lane) g_a[r] = 1.0f;
    }
}

// ================= K4: fused down+up GEMM, BM=96, grid 417 (94% wave balance) ============
// 192 thr = 6 warps (3 warpM x 32 rows, 2 warpN x 32 cols).
// smem bytes: A0[0,13824) A1[13824,27648) B0[27648,36864) B1[36864,46080) sA[46080,46464)
// Row stride 144 B => conflict-free stores and ldmatrix.
#define SM_BYTES 46464
extern __shared__ uint32_t smw[];

__global__ void __launch_bounds__(192, 4)
fused5_k(const float* __restrict__ bdn, const float* __restrict__ bup,
         float* __restrict__ out) {
    uint32_t* Aw0 = smw;
    float*    sA  = (float*)(smw + 11520);   // 46080/4

    const uint32_t sbase = smem_u32(smw);
    const int t = threadIdx.x, wid = t >> 5, lane = t & 31;
    const int warpM = wid % 3, warpN = wid / 3;
    const int row0 = blockIdx.x * 96;

    // ldmatrix per-lane base addresses (byte), stage 0
    const int lr16 = lane & 15, lk16 = (lane >> 4) & 1;
    const uint32_t aAddr0 = sbase + (uint32_t)((warpM * 32 + lr16) * 144 + lk16 * 16);
    const int brr = warpN * 32 + ((lane >> 4) & 1) * 8 + (lane & 7);
    const uint32_t bAddr0 = sbase + 27648 + (uint32_t)(brr * 144 + ((lane >> 3) & 1) * 16);

    // cp.async segment mapping: A 768 segs (4/thread), B 512 segs (2-3/thread)
    const int an0 = t >> 3, aq = t & 7;
    const uint32_t adst = sbase + (uint32_t)(an0 * 144 + aq * 16);
    const uint32_t bdst = sbase + 27648 + (uint32_t)(an0 * 144 + aq * 16);
    const __half* asrc = g_fh + (size_t)(row0 + an0) * 1024 + aq * 8;

    if (t < 96) sA[t] = g_a[row0 + t];

    float acc[8][4];
    #pragma unroll
    for (int i = 0; i < 8; i++)
        #pragma unroll
        for (int j = 0; j < 4; j++) acc[i][j] = 0.f;

    // ---- prologue: chunk 0 into stage 0 ----
    #pragma unroll
    for (int j = 0; j < 4; j++)
        cpasync16(adst + (uint32_t)(j * 24) * 144, asrc + (size_t)(j * 24) * 1024);
    #pragma unroll
    for (int j = 0; j < 3; j++) {
        int idx = t + j * 192;
        if (idx < 512)
            cpasync16(bdst + (uint32_t)(j * 24) * 144, g_wd + (an0 + j * 24) * 64 + aq * 8);
    }
    cp_commit();
    cp_wait0();
    __syncthreads();

    // ============ down phase: 16 chunks of 64, double-buffered ============
    #pragma unroll 1
    for (int c = 0; c < 16; c++) {
        const uint32_t cur = (uint32_t)(c & 1), nxt = cur ^ 1u;
        if (c < 15) {
            const __half* as = asrc + (c + 1) * 64;
            const __half* bs = g_wd + (c + 1) * 4096 + an0 * 64 + aq * 8;
            #pragma unroll
            for (int j = 0; j < 4; j++)
                cpasync16(adst + nxt * 13824u + (uint32_t)(j * 24) * 144, as + (size_t)(j * 24) * 1024);
            #pragma unroll
            for (int j = 0; j < 3; j++) {
                int idx = t + j * 192;
                if (idx < 512)
                    cpasync16(bdst + nxt * 9216u + (uint32_t)(j * 24) * 144, bs + j * 24 * 64);
            }
            cp_commit();
        }
        {
            const uint32_t aA = aAddr0 + cur * 13824u;
            const uint32_t bA = bAddr0 + cur * 9216u;
            #pragma unroll
            for (int ks = 0; ks < 4; ks++) {
                uint32_t af[2][4], bf[2][4];
                ldsm_x4(aA + ks * 32, af[0]);
                ldsm_x4(aA + 16 * 144 + ks * 32, af[1]);
                ldsm_x4(bA + ks * 32, bf[0]);
                ldsm_x4(bA + 16 * 144 + ks * 32, bf[1]);
                #pragma unroll
                for (int mt = 0; mt < 2; mt++)
                    #pragma unroll
                    for (int nt = 0; nt < 4; nt++) {
                        const int n2 = nt >> 1, s = (nt & 1) * 2;
                        mma_f16(acc[mt * 4 + nt], af[mt][0], af[mt][1], af[mt][2], af[mt][3],
                                bf[n2][s], bf[n2][s + 1]);
                    }
            }
        }
        cp_wait0();
        __syncthreads();
    }

    // prefetch up-phase chunk 0 B into stage 0 (B planes free)
    #pragma unroll
    for (int j = 0; j < 3; j++) {
        int idx = t + j * 192;
        if (idx < 512)
            cpasync16(bdst + (uint32_t)(j * 24) * 144, g_wu + (an0 + j * 24) * 64 + aq * 8);
    }
    cp_commit();

    // ---- down epilogue: h = relu(a*dot + b_down) -> fp16 into A stage-0 plane ----
    #pragma unroll
    for (int nt = 0; nt < 4; nt++) {
        const int c0 = warpN * 32 + nt * 8 + (lane & 3) * 2;
        const float bd0 = __ldg(bdn + c0), bd1 = __ldg(bdn + c0 + 1);
        #pragma unroll
        for (int mt = 0; mt < 2; mt++) {
            const float* d = acc[mt * 4 + nt];
            const int rb = warpM * 32 + mt * 16 + (lane >> 2);
            #pragma unroll
            for (int rr = 0; rr < 2; rr++) {
                const int rloc = rb + rr * 8;
                float av2 = sA[rloc];
                float h0 = fmaxf(fmaf(av2, d[rr * 2 + 0], bd0), 0.f);
                float h1 = fmaxf(fmaf(av2, d[rr * 2 + 1], bd1), 0.f);
                Aw0[rloc * 36 + c0 / 2] = pkh2(h0, h1);
            }
        }
    }
    cp_wait0();
    __syncthreads();   // h visible, up-B0 loaded

    // hoist up-phase A (h) fragments: invariant across all 16 N-chunks
    uint32_t afh[4][2][4];
    #pragma unroll
    for (int ks = 0; ks < 4; ks++) {
        ldsm_x4(aAddr0 + ks * 32, afh[ks][0]);
        ldsm_x4(aAddr0 + 16 * 144 + ks * 32, afh[ks][1]);
    }

    // ============ up phase: 16 N-chunks of 64, A = h (regs), B double-buffered ============
    #pragma unroll 1
    for (int nc = 0; nc < 16; nc++) {
        const uint32_t cur = (uint32_t)(nc & 1);
        if (nc < 15) {
            const __half* bs = g_wu + (nc + 1) * 4096 + an0 * 64 + aq * 8;
            const uint32_t bo = (cur ^ 1u) * 9216u;
            #pragma unroll
            for (int j = 0; j < 3; j++) {
                int idx = t + j * 192;
                if (idx < 512)
                    cpasync16(bdst + bo + (uint32_t)(j * 24) * 144, bs + j * 24 * 64);
            }
            cp_commit();
        }
        #pragma unroll
        for (int i = 0; i < 8; i++)
            #pragma unroll
            for (int j = 0; j < 4; j++) acc[i][j] = 0.f;
        {
            const uint32_t bA = bAddr0 + cur * 9216u;
            #pragma unroll
            for (int ks = 0; ks < 4; ks++) {
                uint32_t bf[2][4];
                ldsm_x4(bA + ks * 32, bf[0]);
                ldsm_x4(bA + 16 * 144 + ks * 32, bf[1]);
                #pragma unroll
                for (int mt = 0; mt < 2; mt++)
                    #pragma unroll
                    for (int nt = 0; nt < 4; nt++) {
                        const int n2 = nt >> 1, s = (nt & 1) * 2;
                        mma_f16(acc[mt * 4 + nt], afh[ks][mt][0], afh[ks][mt][1],
                                afh[ks][mt][2], afh[ks][mt][3], bf[n2][s], bf[n2][s + 1]);
                    }
            }
        }
        // epilogue: out = acc + b_up
        const int nb64 = nc * 64;
        #pragma unroll
        for (int nt = 0; nt < 4; nt++) {
            const int c0 = warpN * 32 + nt * 8 + (lane & 3) * 2;
            const float u0 = __ldg(bup + nb64 + c0), u1 = __ldg(bup + nb64 + c0 + 1);
            #pragma unroll
            for (int mt = 0; mt < 2; mt++) {
                const float* d = acc[mt * 4 + nt];
                const int rb = warpM * 32 + mt * 16 + (lane >> 2);
                #pragma unroll
                for (int rr = 0; rr < 2; rr++) {
                    int row = row0 + rb + rr * 8;
                    if (row < ROWS_TOT) {
                        float2 v = make_float2(d[rr * 2 + 0] + u0, d[rr * 2 + 1] + u1);
                        *(float2*)(out + (size_t)row * 1024 + nb64 + c0) = v;
                    }
                }
            }
        }
        cp_wait0();
        __syncthreads();
    }
}

// ---------------- launch ----------------
extern "C" void kernel_launch(void* const* d_in, const int* in_sizes, int n_in,
                              void* d_out, int out_size) {
    (void)in_sizes; (void)n_in; (void)out_size;
    const float* x   = (const float*)d_in[0];
    const float* s_f = (const float*)d_in[1];
    const float* s_y = (const float*)d_in[2];
    const float* P   = (const float*)d_in[3];
    const float* Wd  = (const float*)d_in[4];
    const float* bd  = (const float*)d_in[5];
    const float* Wu  = (const float*)d_in[6];
    const float* bu  = (const float*)d_in[7];
    float* out = (float*)d_out;

    static bool attr_set = false;
    if (!attr_set) {
        cudaFuncSetAttribute(fused5_k, cudaFuncAttributeMaxDynamicSharedMemorySize, SM_BYTES);
        attr_set = true;
    }

    combo_k<<<768, 256>>>(Wd, Wu, s_f, s_y);
    select3_k<<<8, 256>>>(P);
    convert_k<<<5004, 256>>>(x, s_f);
    fused5_k<<<417, 192, SM_BYTES>>>(bd, bu, out);
}